// round 16
// baseline (speedup 1.0000x reference)
#include <cuda_runtime.h>

// GaussianAdapter: smooth[b,r,f] = sum_t(dist*v)/sum_t(dist),
// dist = exp(-alpha*(ref[b,r]-ts[b,t,f])^2)*(ts>0) + 1e-7
// Shapes: B=16, T=512, R=128, F=32 (fixed by the dataset).
//
// With c = -alpha*log2(e): exponent y' = c*(t-r)^2 = ct*(-2r) + (c t^2 + c r^2)
// computed NON-NEGATIVE-FREE (y' <= 0 always) so the packed fp16 MUFU op
// ex2.approx.f16x2 (one MUFU slot per r-PAIR, halving MUFU vs f32 ex2)
// can never overflow -- this fixes round 15's Inf/Inf NaN, which came from
// deferring the 2^(c r^2) scale (unscaled exponent reached +72 > fp16 max).
// No epilogue E fixup needed. Accumulators stay f32x2. Mask via t<-2.2
// (y' <= -103 -> fp16 w == 0 exactly).

#define Bc 16
#define Tc 512
#define Rc 128
#define Fc 32
#define RT 8      // r values per block (4 f32x2 pairs)
#define TG 16     // warps per block
#define NB 8      // t-batches per warp
#define BL 4      // t's per batch  (TG*NB*BL == Tc)
#define EPSF 1e-7f

typedef unsigned long long u64;

__device__ __forceinline__ u64 pk2(float lo, float hi) {
    u64 p;
    asm("mov.b64 %0, {%1,%2};" : "=l"(p)
        : "r"(__float_as_uint(lo)), "r"(__float_as_uint(hi)));
    return p;
}
__device__ __forceinline__ void upk2(u64 p, float& lo, float& hi) {
    unsigned int a, b;
    asm("mov.b64 {%0,%1}, %2;" : "=r"(a), "=r"(b) : "l"(p));
    lo = __uint_as_float(a); hi = __uint_as_float(b);
}
__device__ __forceinline__ u64 fma2(u64 a, u64 b, u64 c) {
    u64 d;
    asm("fma.rn.f32x2 %0, %1, %2, %3;" : "=l"(d) : "l"(a), "l"(b), "l"(c));
    return d;
}
__device__ __forceinline__ u64 add2(u64 a, u64 b) {
    u64 d;
    asm("add.rn.f32x2 %0, %1, %2;" : "=l"(d) : "l"(a), "l"(b));
    return d;
}

// Packed-pair exp2: f32x2 y -> f32x2 2^y via ONE ex2.approx.f16x2 (MUFU).
// Requires y <= 0 (guaranteed by construction: y = c*(t-r)^2, c < 0).
// cvt.rn.f16x2.f32 d, a, b packs d = {lo: cvt(b), hi: cvt(a)}.
__device__ __forceinline__ u64 ex2h_pair(u64 y2) {
    u64 w2;
    asm("{\n\t"
        ".reg .f32 y0, y1, w0, w1;\n\t"
        ".reg .b32 p;\n\t"
        ".reg .b16 l, h;\n\t"
        "mov.b64 {y0, y1}, %1;\n\t"
        "cvt.rn.f16x2.f32 p, y1, y0;\n\t"
        "ex2.approx.f16x2 p, p;\n\t"
        "mov.b32 {l, h}, p;\n\t"
        "cvt.f32.f16 w0, l;\n\t"
        "cvt.f32.f16 w1, h;\n\t"
        "mov.b64 %0, {w0, w1};\n\t"
        "}" : "=l"(w2) : "l"(y2));
    return w2;
}

__global__ __launch_bounds__(TG * Fc, 2) void gaussian_adapter_kernel(
    const float* __restrict__ ts,     // [B,T,F]
    const float* __restrict__ vals,   // [B,T,F]
    const float* __restrict__ ref,    // [B,R]
    const float* __restrict__ alpha,  // [1]
    float* __restrict__ out)          // [B,R,F]
{
    const int b  = blockIdx.y;
    const int r0 = blockIdx.x * RT;
    const int f  = threadIdx.x & (Fc - 1);
    const int tg = threadIdx.x >> 5;

    const float a = alpha[0];
    const float c = -a * 1.44269504088896340736f;  // -alpha * log2(e)

    // Per r-pair loop invariants: rn[i] = -2*r (packed), cr2[i] = c*r^2 (packed)
    u64 rn[RT / 2], cr2[RT / 2];
#pragma unroll
    for (int i = 0; i < RT / 2; i++) {
        const float ra = __ldg(&ref[b * Rc + r0 + 2 * i]);
        const float rb = __ldg(&ref[b * Rc + r0 + 2 * i + 1]);
        rn[i]  = pk2(-2.0f * ra, -2.0f * rb);
        cr2[i] = pk2(c * ra * ra, c * rb * rb);
    }

    u64 num[RT / 2], den[RT / 2];
#pragma unroll
    for (int i = 0; i < RT / 2; i++) { num[i] = 0ull; den[i] = 0ull; }
    float sv = 0.f;  // sum of v over this warp's t-slice (for eps term)

    const float* tsb = ts   + (size_t)b * Tc * Fc + (size_t)tg * Fc + f;
    const float* vb  = vals + (size_t)b * Tc * Fc + (size_t)tg * Fc + f;
    const int STRD = TG * Fc;  // stride between this warp's consecutive t's

    float tbuf[2][BL], vbuf[2][BL];

    // prologue: load batch 0
#pragma unroll
    for (int j = 0; j < BL; j++) {
        tbuf[0][j] = __ldg(tsb + j * STRD);
        vbuf[0][j] = __ldg(vb  + j * STRD);
    }

#pragma unroll
    for (int batch = 0; batch < NB; batch++) {
        const int cur = batch & 1;
        const int nxt = cur ^ 1;
        if (batch + 1 < NB) {
            const int base = (batch + 1) * BL;
#pragma unroll
            for (int j = 0; j < BL; j++) {
                tbuf[nxt][j] = __ldg(tsb + (base + j) * STRD);
                vbuf[nxt][j] = __ldg(vb  + (base + j) * STRD);
            }
        }
#pragma unroll
        for (int j = 0; j < BL; j++) {
            const float tv  = tbuf[cur][j];
            const float vv  = vbuf[cur][j];
            const float tvm = (tv > 0.f) ? tv : 2.2f;  // masked -> w==0 in fp16
            const float ct  = c * tvm;
            const float u   = ct * tvm;       // c t^2
            sv += vv;

            const u64 ct2 = pk2(ct, ct);
            const u64 u2  = pk2(u, u);
            const u64 v2  = pk2(vv, vv);

#pragma unroll
            for (int i = 0; i < RT / 2; i++) {
                const u64 uc2 = add2(u2, cr2[i]);     // c t^2 + c r^2
                const u64 y2  = fma2(ct2, rn[i], uc2); // = c (t-r)^2 <= 0
                const u64 w2  = ex2h_pair(y2);         // one MUFU op per pair
                den[i] = add2(den[i], w2);
                num[i] = fma2(w2, v2, num[i]);
            }
        }
    }

    // Reduce the TG t-groups per (r,f)
    __shared__ float sn[TG][RT][Fc];
    __shared__ float sd[TG][RT][Fc];
    __shared__ float ssv[TG][Fc];
#pragma unroll
    for (int i = 0; i < RT / 2; i++) {
        float x0, x1;
        upk2(num[i], x0, x1); sn[tg][2 * i][f] = x0; sn[tg][2 * i + 1][f] = x1;
        upk2(den[i], x0, x1); sd[tg][2 * i][f] = x0; sd[tg][2 * i + 1][f] = x1;
    }
    ssv[tg][f] = sv;
    __syncthreads();

    if (threadIdx.x < RT * Fc) {
        const int ri = threadIdx.x >> 5;  // which r within tile
        float n = 0.f, d = 0.f, svt = 0.f;
#pragma unroll
        for (int g = 0; g < TG; g++) {
            n   += sn[g][ri][f];
            d   += sd[g][ri][f];
            svt += ssv[g][f];
        }
        const float den_t = d + (float)Tc * EPSF;
        const float num_t = fmaf(EPSF, svt, n);
        out[(size_t)b * Rc * Fc + (r0 + ri) * Fc + f] = num_t / den_t;
    }
}

extern "C" void kernel_launch(void* const* d_in, const int* in_sizes, int n_in,
                              void* d_out, int out_size) {
    const float* ts    = (const float*)d_in[0];
    const float* vals  = (const float*)d_in[1];
    const float* ref   = (const float*)d_in[2];
    const float* alpha = (const float*)d_in[3];
    float* out = (float*)d_out;

    dim3 grid(Rc / RT, Bc);
    dim3 block(TG * Fc);
    gaussian_adapter_kernel<<<grid, block>>>(ts, vals, ref, alpha, out);
}

// round 17
// speedup vs baseline: 1.0243x; 1.0243x over previous
#include <cuda_runtime.h>

// GaussianAdapter: smooth[b,r,f] = sum_t(dist*v)/sum_t(dist),
// dist = exp(-alpha*(ref[b,r]-ts[b,t,f])^2)*(ts>0) + 1e-7
// Shapes: B=16, T=512, R=128, F=32 (fixed by the dataset).
//
// Round-9 math (proven 12.8us): with c = -alpha*log2(e),
//   exp(-a(r-t)^2) = 2^(c r^2) * 2^(ct*(-2 r) + c t^2)
// unscaled f32 accumulation (exponent may reach +72 -> f32 only), E-scale +
// eps fixup applied in the BLOCK epilogue so cross-block partials are final-
// scaled and just sum.
//
// New: t-dim split x4 -> 1024 blocks x 128 thr (vs 256 blocks) to kill the
// 256-on-148-SM placement quantization (x1.157 -> x1.012). Partials go to
// per-slot __device__ scratch (no atomics, no zeroing); the last of the 4
// blocks per (b,rtile) pair (threadfence-reduction counter) sums 4 slots,
// divides, stores, and resets its counter to 0 (graph-replay safe).

#define Bc 16
#define Tc 512
#define Rc 128
#define Fc 32
#define RT 8      // r values per block (4 f32x2 pairs)
#define TG 4      // warps per block
#define ST 4      // t-split factor (blocks per (b,rtile) pair)
#define TQ (Tc / ST)          // t's per block = 128
#define NB 8      // t-batches per warp
#define BL 4      // t's per batch  (TG*NB*BL == TQ)
#define NPAIR (Bc * (Rc / RT))  // 256 (b,rtile) pairs
#define EPSF 1e-7f

typedef unsigned long long u64;

// Cross-block scratch: per t-slice slot, per pair, per (r,f). ~2MB.
__device__ float g_pn[ST][NPAIR][RT][Fc];
__device__ float g_pd[ST][NPAIR][RT][Fc];
__device__ int   g_cnt[NPAIR];   // zero-init; returns to 0 every run

__device__ __forceinline__ u64 pk2(float lo, float hi) {
    u64 p;
    asm("mov.b64 %0, {%1,%2};" : "=l"(p)
        : "r"(__float_as_uint(lo)), "r"(__float_as_uint(hi)));
    return p;
}
__device__ __forceinline__ void upk2(u64 p, float& lo, float& hi) {
    unsigned int a, b;
    asm("mov.b64 {%0,%1}, %2;" : "=r"(a), "=r"(b) : "l"(p));
    lo = __uint_as_float(a); hi = __uint_as_float(b);
}
__device__ __forceinline__ u64 fma2(u64 a, u64 b, u64 c) {
    u64 d;
    asm("fma.rn.f32x2 %0, %1, %2, %3;" : "=l"(d) : "l"(a), "l"(b), "l"(c));
    return d;
}
__device__ __forceinline__ u64 add2(u64 a, u64 b) {
    u64 d;
    asm("add.rn.f32x2 %0, %1, %2;" : "=l"(d) : "l"(a), "l"(b));
    return d;
}
__device__ __forceinline__ float ex2f(float x) {
    float w;
    asm("ex2.approx.ftz.f32 %0, %1;" : "=f"(w) : "f"(x));
    return w;
}

__global__ __launch_bounds__(TG * Fc, 7) void gaussian_adapter_kernel(
    const float* __restrict__ ts,     // [B,T,F]
    const float* __restrict__ vals,   // [B,T,F]
    const float* __restrict__ ref,    // [B,R]
    const float* __restrict__ alpha,  // [1]
    float* __restrict__ out)          // [B,R,F]
{
    const int b    = blockIdx.y;
    const int r0   = blockIdx.x * RT;
    const int s    = blockIdx.z;          // t-quarter
    const int pair = b * (Rc / RT) + blockIdx.x;
    const int f  = threadIdx.x & (Fc - 1);
    const int tg = threadIdx.x >> 5;

    const float a = alpha[0];
    const float c = -a * 1.44269504088896340736f;  // -alpha * log2(e)

    // rn[i] = -2 * r_i, packed in pairs (loop-invariant multiplier of ct)
    u64 rn[RT / 2];
#pragma unroll
    for (int i = 0; i < RT / 2; i++) {
        const float ra = __ldg(&ref[b * Rc + r0 + 2 * i]);
        const float rb = __ldg(&ref[b * Rc + r0 + 2 * i + 1]);
        rn[i] = pk2(-2.0f * ra, -2.0f * rb);
    }

    u64 num[RT / 2], den[RT / 2];
#pragma unroll
    for (int i = 0; i < RT / 2; i++) { num[i] = 0ull; den[i] = 0ull; }
    float sv = 0.f;  // sum of v over this warp's t-slice (for eps term)

    // This block's t-range: [s*TQ, (s+1)*TQ); warp tg strides by TG within it.
    const float* tsb = ts   + (size_t)b * Tc * Fc + (size_t)(s * TQ + tg) * Fc + f;
    const float* vb  = vals + (size_t)b * Tc * Fc + (size_t)(s * TQ + tg) * Fc + f;
    const int STRD = TG * Fc;

    float tbuf[2][BL], vbuf[2][BL];

    // prologue: load batch 0
#pragma unroll
    for (int j = 0; j < BL; j++) {
        tbuf[0][j] = __ldg(tsb + j * STRD);
        vbuf[0][j] = __ldg(vb  + j * STRD);
    }

#pragma unroll
    for (int batch = 0; batch < NB; batch++) {
        const int cur = batch & 1;
        const int nxt = cur ^ 1;
        if (batch + 1 < NB) {
            const int base = (batch + 1) * BL;
#pragma unroll
            for (int j = 0; j < BL; j++) {
                tbuf[nxt][j] = __ldg(tsb + (base + j) * STRD);
                vbuf[nxt][j] = __ldg(vb  + (base + j) * STRD);
            }
        }
#pragma unroll
        for (int j = 0; j < BL; j++) {
            const float tv  = tbuf[cur][j];
            const float vv  = vbuf[cur][j];
            const float tvm = (tv > 0.f) ? tv : 1.0e3f;  // masked t -> w==0
            const float ct  = c * tvm;
            const float u   = ct * tvm;       // c t^2
            sv += vv;

            const u64 ct2 = pk2(ct, ct);
            const u64 u2  = pk2(u, u);
            const u64 v2  = pk2(vv, vv);

#pragma unroll
            for (int i = 0; i < RT / 2; i++) {
                const u64 y2 = fma2(ct2, rn[i], u2);  // ct*(-2r) + c t^2
                float y0, y1;
                upk2(y2, y0, y1);
                const u64 w2 = pk2(ex2f(y0), ex2f(y1));
                den[i] = add2(den[i], w2);
                num[i] = fma2(w2, v2, num[i]);
            }
        }
    }

    // Reduce the TG t-groups per (r,f) inside the block
    __shared__ float sn[TG][RT][Fc];
    __shared__ float sd[TG][RT][Fc];
    __shared__ float ssv[TG][Fc];
    __shared__ int   s_last;
#pragma unroll
    for (int i = 0; i < RT / 2; i++) {
        float x0, x1;
        upk2(num[i], x0, x1); sn[tg][2 * i][f] = x0; sn[tg][2 * i + 1][f] = x1;
        upk2(den[i], x0, x1); sd[tg][2 * i][f] = x0; sd[tg][2 * i + 1][f] = x1;
    }
    ssv[tg][f] = sv;
    __syncthreads();

    // Each thread finalizes RT/TG = 2 r's: apply E-scale + this slice's eps
    // share, store to this block's scratch slot.
#pragma unroll
    for (int ri = tg; ri < RT; ri += TG) {
        float n = 0.f, d = 0.f, svt = 0.f;
#pragma unroll
        for (int g = 0; g < TG; g++) {
            n   += sn[g][ri][f];
            d   += sd[g][ri][f];
            svt += ssv[g][f];
        }
        const float rr = __ldg(&ref[b * Rc + r0 + ri]);
        const float E  = ex2f(c * rr * rr);
        g_pd[s][pair][ri][f] = fmaf(E, d, (float)TQ * EPSF);
        g_pn[s][pair][ri][f] = fmaf(E, n, EPSF * svt);
    }
    __syncthreads();

    // Threadfence reduction: last block of the 4 for this pair combines.
    if (threadIdx.x == 0) {
        __threadfence();
        const int old = atomicAdd(&g_cnt[pair], 1);
        s_last = (old == ST - 1);
    }
    __syncthreads();

    if (s_last) {
        __threadfence();  // acquire: see all 4 slots
#pragma unroll
        for (int ri = tg; ri < RT; ri += TG) {
            float n = 0.f, d = 0.f;
#pragma unroll
            for (int q = 0; q < ST; q++) {
                n += g_pn[q][pair][ri][f];
                d += g_pd[q][pair][ri][f];
            }
            out[(size_t)b * Rc * Fc + (r0 + ri) * Fc + f] = n / d;
        }
        if (threadIdx.x == 0) atomicExch(&g_cnt[pair], 0);  // replay-safe reset
    }
}

extern "C" void kernel_launch(void* const* d_in, const int* in_sizes, int n_in,
                              void* d_out, int out_size) {
    const float* ts    = (const float*)d_in[0];
    const float* vals  = (const float*)d_in[1];
    const float* ref   = (const float*)d_in[2];
    const float* alpha = (const float*)d_in[3];
    float* out = (float*)d_out;

    dim3 grid(Rc / RT, Bc, ST);
    dim3 block(TG * Fc);
    gaussian_adapter_kernel<<<grid, block>>>(ts, vals, ref, alpha, out);
}